// round 11
// baseline (speedup 1.0000x reference)
#include <cuda_runtime.h>
#include <cstdio>

#define Bb 64
#define Pp 10000
#define Ee 128
#define Cc 100
#define CAP 384
#define BC (Bb*Cc)

// ---------------- scratch (no allocations allowed) ----------------
__device__ int   g_cnt[BC];
__device__ int   g_idx[BC*CAP];
__device__ float g_means[BC*Ee];
__device__ float g_wt[Ee*Ee];        // W transposed: g_wt[k*Ee+e] = W[e*Ee+k]
__device__ int   g_ids[Bb*Pp];
__device__ int   g_is64;

__device__ __forceinline__ void f4add(float4& a, const float4 b) {
    a.x += b.x; a.y += b.y; a.z += b.z; a.w += b.w;
}

// ---------------- K0: zero counters + W transpose + dtype detect ----------------
__global__ void k_init(const int* __restrict__ ids32, const float* __restrict__ W) {
    int i = blockIdx.x * blockDim.x + threadIdx.x;
    if (i < BC) g_cnt[i] = 0;
    if (i < Ee*Ee) {                      // one-time scattered transpose (tiny)
        int k = i >> 7, e = i & 127;
        g_wt[i] = W[e*Ee + k];
    }
    if (i == 0) {
        int all0 = 1;
        #pragma unroll 4
        for (int j = 0; j < 64; j++) {
            if (ids32[2*j + 1] != 0) { all0 = 0; break; }
        }
        g_is64 = all0;
    }
}

// ---------------- K1: bucket node indices by (batch, cluster) ----------------
__global__ void k_bucket(const void* __restrict__ ids_raw) {
    int i = blockIdx.x * blockDim.x + threadIdx.x;   // over B*P
    if (i >= Bb*Pp) return;
    int c;
    if (g_is64) c = (int)((const long long*)ids_raw)[i];
    else        c = ((const int*)ids_raw)[i];
    g_ids[i] = c;
    int b = i / Pp;
    int pos = atomicAdd(&g_cnt[b*Cc + c], 1);
    if (pos < CAP) g_idx[(b*Cc + c)*CAP + pos] = i - b*Pp;
}

// ---------------- K2: segment mean (float4 rows, warp-per-row, MLP=4) ----------------
__global__ void __launch_bounds__(128) k_mean(const float* __restrict__ enc) {
    int bc   = blockIdx.x;            // (b, c)
    int b    = bc / Cc;
    int warp = threadIdx.x >> 5;
    int lane = threadIdx.x & 31;

    __shared__ int    s_idx[CAP];
    __shared__ float4 s_red[3][32];

    int n_full = g_cnt[bc];
    int n = n_full < CAP ? n_full : CAP;
    for (int i = threadIdx.x; i < n; i += 128) s_idx[i] = g_idx[bc*CAP + i];
    __syncthreads();

    const float4* __restrict__ base4 = (const float4*)(enc + (size_t)b * Pp * Ee);
    float4 a0 = {0,0,0,0}, a1 = a0, a2 = a0, a3 = a0;

    int i = warp;
    for (; i + 12 < n; i += 16) {
        float4 v0 = __ldcs(&base4[(size_t)s_idx[i     ]*32 + lane]);
        float4 v1 = __ldcs(&base4[(size_t)s_idx[i +  4]*32 + lane]);
        float4 v2 = __ldcs(&base4[(size_t)s_idx[i +  8]*32 + lane]);
        float4 v3 = __ldcs(&base4[(size_t)s_idx[i + 12]*32 + lane]);
        f4add(a0, v0); f4add(a1, v1); f4add(a2, v2); f4add(a3, v3);
    }
    for (; i < n; i += 4)
        f4add(a0, __ldcs(&base4[(size_t)s_idx[i]*32 + lane]));

    f4add(a0, a1); f4add(a2, a3); f4add(a0, a2);

    if (warp) s_red[warp-1][lane] = a0;
    __syncthreads();
    if (warp == 0) {
        f4add(a0, s_red[0][lane]);
        f4add(a0, s_red[1][lane]);
        f4add(a0, s_red[2][lane]);
        float inv = 1.f / (float)(n_full > 0 ? n_full : 1);
        a0.x *= inv; a0.y *= inv; a0.z *= inv; a0.w *= inv;
        ((float4*)g_means)[(size_t)bc*32 + lane] = a0;
    }
}

// ---------------- K3: projection GEMM  out = means @ W^T + b ----------------
// v5: K-SPLIT=4. 16 rows x 128 cols per block, 512 threads (16 warps): thread
// group h (128 threads) accumulates k in [32h, 32h+32). Groups 1-3 write
// partials to padded smem; group 0 combines + bias + store. 32 warps/SM keeps
// 8 eligible warps per SMSP so the FFMA pipe (rt=2) issues at full rate.
#define SWS 132                                  // padded k-row stride (floats)
#define PROJ_SMEM ((16*Ee + Ee*SWS) * 4)         // 8KB + 67.6KB = 75.6KB
__global__ void __launch_bounds__(512) k_proj(const float* __restrict__ bias,
                                              float* __restrict__ ce) {
    extern __shared__ float smem[];
    float* sM = smem;                  // [16][Ee]
    float* sW = smem + 16*Ee;          // [Ee][SWS] k-major, padded

    int tid = threadIdx.x;
    int row_base = blockIdx.x * 16;

    // stage 16 mean rows (float4, coalesced)
    const float4* gm4 = (const float4*)(g_means + (size_t)row_base*Ee);
    float4* sM4 = (float4*)sM;
    for (int j = tid; j < 16*Ee/4; j += 512) sM4[j] = gm4[j];

    // stage Wt: compact [k][e] -> padded [k][SWS] (coalesced LDG.128 / STS.128)
    const float4* wt4 = (const float4*)g_wt;
    for (int j = tid; j < Ee*Ee/4; j += 512) {
        int k = j >> 5, q = j & 31;
        ((float4*)(sW + k*SWS))[q] = wt4[j];
    }
    __syncthreads();

    int half = tid >> 7;               // k-quarter: 0..3
    int t    = tid & 127;
    int cg   = t & 31;                 // cols 4*cg .. 4*cg+3
    int rg   = t >> 5;                 // rows 4*rg .. 4*rg+3
    int kbase = half * 8;              // in k4 units (8 k4 = 32 k per group)

    float4 acc[4] = {{0,0,0,0},{0,0,0,0},{0,0,0,0},{0,0,0,0}};

    #pragma unroll
    for (int k4 = 0; k4 < 8; k4++) {
        float4 m[4], w[4];
        #pragma unroll
        for (int r = 0; r < 4; r++)
            m[r] = sM4[(rg*4 + r)*32 + kbase + k4];              // warp broadcast
        #pragma unroll
        for (int j = 0; j < 4; j++)
            w[j] = *(const float4*)(sW + ((kbase + k4)*4 + j)*SWS + cg*4);
        #pragma unroll
        for (int r = 0; r < 4; r++) {
            acc[r].x += m[r].x*w[0].x + m[r].y*w[1].x + m[r].z*w[2].x + m[r].w*w[3].x;
            acc[r].y += m[r].x*w[0].y + m[r].y*w[1].y + m[r].z*w[2].y + m[r].w*w[3].y;
            acc[r].z += m[r].x*w[0].z + m[r].y*w[1].z + m[r].z*w[2].z + m[r].w*w[3].z;
            acc[r].w += m[r].x*w[0].w + m[r].y*w[1].w + m[r].z*w[2].w + m[r].w*w[3].w;
        }
    }

    // combine the four k-quarters through smem (reuse sW; pad-5 => conflict-free)
    __syncthreads();
    float4* sR = (float4*)sW;          // 3 regions of [128][5] float4 (30KB of sW)
    if (half != 0) {
        float4* dst = sR + (half - 1) * 128 * 5;
        #pragma unroll
        for (int r = 0; r < 4; r++) dst[t*5 + r] = acc[r];
    }
    __syncthreads();
    if (half == 0) {
        float4 bb = ((const float4*)bias)[cg];
        #pragma unroll
        for (int h = 0; h < 3; h++) {
            const float4* src = sR + h * 128 * 5;
            #pragma unroll
            for (int r = 0; r < 4; r++) f4add(acc[r], src[t*5 + r]);
        }
        #pragma unroll
        for (int r = 0; r < 4; r++) {
            f4add(acc[r], bb);
            ((float4*)(ce + (size_t)(row_base + rg*4 + r)*Ee))[cg] = acc[r];
        }
    }
}

// ---------------- K4: gather projected cluster embs back to nodes ----------------
#define PCH 625
#define GATHER_SMEM ((Cc*Ee + PCH + 3) * 4)
__global__ void __launch_bounds__(256) k_gather(const float* __restrict__ ce,
                                                float* __restrict__ gn) {
    extern __shared__ float s_dyn[];
    float* s_tab = s_dyn;                       // [Cc][Ee]
    int*   s_id  = (int*)(s_dyn + Cc*Ee);       // [PCH]

    int b  = blockIdx.y;
    int p0 = blockIdx.x * PCH;
    int cnt = Pp - p0; if (cnt > PCH) cnt = PCH;

    const float4* __restrict__ cb4 = (const float4*)(ce + (size_t)b * Cc * Ee);
    for (int j = threadIdx.x; j < Cc*Ee/4; j += 256)
        ((float4*)s_tab)[j] = cb4[j];
    const int* __restrict__ idb = g_ids + b*Pp + p0;
    for (int j = threadIdx.x; j < cnt; j += 256)
        s_id[j] = idb[j];
    __syncthreads();

    int lane = threadIdx.x & 31;
    int warp = threadIdx.x >> 5;
    float4* __restrict__ out = (float4*)(gn + ((size_t)b*Pp + p0)*Ee);

    int p = warp;
    for (; p + 8 < cnt; p += 16) {
        int c0 = s_id[p], c1 = s_id[p + 8];
        float4 v0 = ((const float4*)(s_tab + c0*Ee))[lane];
        float4 v1 = ((const float4*)(s_tab + c1*Ee))[lane];
        __stcs(&out[(size_t)p      *32 + lane], v0);
        __stcs(&out[(size_t)(p + 8)*32 + lane], v1);
    }
    for (; p < cnt; p += 8) {
        int c = s_id[p];
        float4 v = ((const float4*)(s_tab + c*Ee))[lane];
        __stcs(&out[(size_t)p*32 + lane], v);
    }
}

// ---------------- launch ----------------
extern "C" void kernel_launch(void* const* d_in, const int* in_sizes, int n_in,
                              void* d_out, int out_size) {
    const float* enc  = nullptr;
    const void*  ids  = nullptr;
    const float* W    = nullptr;
    const float* bias = nullptr;
    for (int i = 0; i < n_in; i++) {
        switch (in_sizes[i]) {
            case Bb*Pp*Ee: enc  = (const float*)d_in[i]; break;
            case Bb*Pp:    ids  = d_in[i];               break;
            case Ee*Ee:    W    = (const float*)d_in[i]; break;
            case Ee:       bias = (const float*)d_in[i]; break;
            default: break;
        }
    }

    float* ce = (float*)d_out;                       // [B, C, E]
    float* gn = (float*)d_out + (size_t)BC * Ee;     // [B, P, E]

    cudaFuncSetAttribute(k_proj,   cudaFuncAttributeMaxDynamicSharedMemorySize, PROJ_SMEM);
    cudaFuncSetAttribute(k_gather, cudaFuncAttributeMaxDynamicSharedMemorySize, GATHER_SMEM);

    k_init  <<<(Ee*Ee + 255)/256, 256>>>((const int*)ids, W);
    k_bucket<<<(Bb*Pp + 255)/256, 256>>>(ids);
    k_mean  <<<BC, 128>>>(enc);
    k_proj  <<<BC/16, 512, PROJ_SMEM>>>(bias, ce);
    k_gather<<<dim3((Pp + PCH - 1)/PCH, Bb), 256, GATHER_SMEM>>>(ce, gn);
}

// round 13
// speedup vs baseline: 1.0401x; 1.0401x over previous
#include <cuda_runtime.h>
#include <cstdio>

#define Bb 64
#define Pp 10000
#define Ee 128
#define Cc 100
#define CAP 384
#define BC (Bb*Cc)

// ---------------- scratch (no allocations allowed) ----------------
__device__ int   g_cnt[BC];
__device__ int   g_idx[BC*CAP];
__device__ float g_means[BC*Ee];
__device__ float g_wt[Ee*Ee];        // W transposed: g_wt[k*Ee+e] = W[e*Ee+k]
__device__ int   g_ids[Bb*Pp];
__device__ int   g_is64;

__device__ __forceinline__ void f4add(float4& a, const float4 b) {
    a.x += b.x; a.y += b.y; a.z += b.z; a.w += b.w;
}

// ---------------- K0: zero counters + W transpose + dtype detect ----------------
__global__ void k_init(const int* __restrict__ ids32, const float* __restrict__ W) {
    int i = blockIdx.x * blockDim.x + threadIdx.x;
    if (i < BC) g_cnt[i] = 0;
    if (i < Ee*Ee) {                      // one-time scattered transpose (tiny)
        int k = i >> 7, e = i & 127;
        g_wt[i] = W[e*Ee + k];
    }
    if (i == 0) {
        int all0 = 1;
        #pragma unroll 4
        for (int j = 0; j < 64; j++) {
            if (ids32[2*j + 1] != 0) { all0 = 0; break; }
        }
        g_is64 = all0;
    }
}

// ---------------- K1: bucket node indices by (batch, cluster) ----------------
__global__ void k_bucket(const void* __restrict__ ids_raw) {
    int i = blockIdx.x * blockDim.x + threadIdx.x;   // over B*P
    if (i >= Bb*Pp) return;
    int c;
    if (g_is64) c = (int)((const long long*)ids_raw)[i];
    else        c = ((const int*)ids_raw)[i];
    g_ids[i] = c;
    int b = i / Pp;
    int pos = atomicAdd(&g_cnt[b*Cc + c], 1);
    if (pos < CAP) g_idx[(b*Cc + c)*CAP + pos] = i - b*Pp;
}

// ---------------- K2: segment mean (float4 rows, warp-per-row, MLP=8) ----------------
__global__ void __launch_bounds__(128) k_mean(const float* __restrict__ enc) {
    int bc   = blockIdx.x;            // (b, c)
    int b    = bc / Cc;
    int warp = threadIdx.x >> 5;
    int lane = threadIdx.x & 31;

    __shared__ int    s_idx[CAP];
    __shared__ float4 s_red[3][32];

    int n_full = g_cnt[bc];
    int n = n_full < CAP ? n_full : CAP;
    for (int i = threadIdx.x; i < n; i += 128) s_idx[i] = g_idx[bc*CAP + i];
    __syncthreads();

    const float4* __restrict__ base4 = (const float4*)(enc + (size_t)b * Pp * Ee);
    float4 a0 = {0,0,0,0}, a1 = a0, a2 = a0, a3 = a0;

    int i = warp;
    // 8 loads in flight per warp (MLP=8) against 577-cyc DRAM latency
    for (; i + 28 < n; i += 32) {
        float4 v0 = __ldcs(&base4[(size_t)s_idx[i     ]*32 + lane]);
        float4 v1 = __ldcs(&base4[(size_t)s_idx[i +  4]*32 + lane]);
        float4 v2 = __ldcs(&base4[(size_t)s_idx[i +  8]*32 + lane]);
        float4 v3 = __ldcs(&base4[(size_t)s_idx[i + 12]*32 + lane]);
        float4 v4 = __ldcs(&base4[(size_t)s_idx[i + 16]*32 + lane]);
        float4 v5 = __ldcs(&base4[(size_t)s_idx[i + 20]*32 + lane]);
        float4 v6 = __ldcs(&base4[(size_t)s_idx[i + 24]*32 + lane]);
        float4 v7 = __ldcs(&base4[(size_t)s_idx[i + 28]*32 + lane]);
        f4add(a0, v0); f4add(a1, v1); f4add(a2, v2); f4add(a3, v3);
        f4add(a0, v4); f4add(a1, v5); f4add(a2, v6); f4add(a3, v7);
    }
    for (; i + 12 < n; i += 16) {
        float4 v0 = __ldcs(&base4[(size_t)s_idx[i     ]*32 + lane]);
        float4 v1 = __ldcs(&base4[(size_t)s_idx[i +  4]*32 + lane]);
        float4 v2 = __ldcs(&base4[(size_t)s_idx[i +  8]*32 + lane]);
        float4 v3 = __ldcs(&base4[(size_t)s_idx[i + 12]*32 + lane]);
        f4add(a0, v0); f4add(a1, v1); f4add(a2, v2); f4add(a3, v3);
    }
    for (; i < n; i += 4)
        f4add(a0, __ldcs(&base4[(size_t)s_idx[i]*32 + lane]));

    f4add(a0, a1); f4add(a2, a3); f4add(a0, a2);

    if (warp) s_red[warp-1][lane] = a0;
    __syncthreads();
    if (warp == 0) {
        f4add(a0, s_red[0][lane]);
        f4add(a0, s_red[1][lane]);
        f4add(a0, s_red[2][lane]);
        float inv = 1.f / (float)(n_full > 0 ? n_full : 1);
        a0.x *= inv; a0.y *= inv; a0.z *= inv; a0.w *= inv;
        ((float4*)g_means)[(size_t)bc*32 + lane] = a0;
    }
}

// ---------------- K3: projection GEMM  out = means @ W^T + b ----------------
// v6: K-split=2, UNPADDED sW (staging copy and w-row loads are both row-
// contiguous -> conflict-free without padding). smem 72KB -> 3 CTAs/SM (R9's
// 75.6KB x3 = 226.9KB didn't fit the usable cap). launch_bounds(256,3) caps
// regs at 85 so 3 CTAs always fit; full unroll lets ptxas hoist LDS early.
#define PROJ_SMEM ((16*Ee + Ee*Ee) * 4)          // 8KB + 64KB = 72KB
__global__ void __launch_bounds__(256, 3) k_proj(const float* __restrict__ bias,
                                                 float* __restrict__ ce) {
    extern __shared__ float smem[];
    float* sM = smem;                  // [16][Ee]
    float* sW = smem + 16*Ee;          // [Ee][Ee] k-major, unpadded

    int tid = threadIdx.x;
    int row_base = blockIdx.x * 16;

    // stage 16 mean rows (float4, coalesced)
    const float4* gm4 = (const float4*)(g_means + (size_t)row_base*Ee);
    float4* sM4 = (float4*)sM;
    for (int j = tid; j < 16*Ee/4; j += 256) sM4[j] = gm4[j];

    // stage Wt: straight float4 copy (coalesced LDG.128 / conflict-free STS.128)
    const float4* wt4 = (const float4*)g_wt;
    float4* sW4 = (float4*)sW;
    for (int j = tid; j < Ee*Ee/4; j += 256) sW4[j] = wt4[j];
    __syncthreads();

    int half = tid >> 7;               // k-half: 0 or 1
    int t    = tid & 127;
    int cg   = t & 31;                 // cols 4*cg .. 4*cg+3
    int rg   = t >> 5;                 // rows 4*rg .. 4*rg+3
    int kbase = half * 16;             // in k4 units

    float4 acc[4] = {{0,0,0,0},{0,0,0,0},{0,0,0,0},{0,0,0,0}};

    #pragma unroll
    for (int k4 = 0; k4 < 16; k4++) {
        float4 m[4], w[4];
        #pragma unroll
        for (int r = 0; r < 4; r++)
            m[r] = sM4[(rg*4 + r)*32 + kbase + k4];              // warp broadcast
        #pragma unroll
        for (int j = 0; j < 4; j++)
            w[j] = sW4[((kbase + k4)*4 + j)*32 + cg];            // row-contiguous
        #pragma unroll
        for (int r = 0; r < 4; r++) {
            acc[r].x += m[r].x*w[0].x + m[r].y*w[1].x + m[r].z*w[2].x + m[r].w*w[3].x;
            acc[r].y += m[r].x*w[0].y + m[r].y*w[1].y + m[r].z*w[2].y + m[r].w*w[3].y;
            acc[r].z += m[r].x*w[0].z + m[r].y*w[1].z + m[r].z*w[2].z + m[r].w*w[3].z;
            acc[r].w += m[r].x*w[0].w + m[r].y*w[1].w + m[r].z*w[2].w + m[r].w*w[3].w;
        }
    }

    // combine the two k-halves through smem (reuse sW; pad-5 => conflict-free)
    __syncthreads();
    float4* sR = (float4*)sW;          // [128][5] float4 (10KB of sW)
    if (half == 1) {
        #pragma unroll
        for (int r = 0; r < 4; r++) sR[t*5 + r] = acc[r];
    }
    __syncthreads();
    if (half == 0) {
        float4 bb = ((const float4*)bias)[cg];
        #pragma unroll
        for (int r = 0; r < 4; r++) {
            f4add(acc[r], sR[t*5 + r]);
            f4add(acc[r], bb);
            ((float4*)(ce + (size_t)(row_base + rg*4 + r)*Ee))[cg] = acc[r];
        }
    }
}

// ---------------- K4: gather projected cluster embs back to nodes ----------------
#define PCH 625
#define GATHER_SMEM ((Cc*Ee + PCH + 3) * 4)
__global__ void __launch_bounds__(256) k_gather(const float* __restrict__ ce,
                                                float* __restrict__ gn) {
    extern __shared__ float s_dyn[];
    float* s_tab = s_dyn;                       // [Cc][Ee]
    int*   s_id  = (int*)(s_dyn + Cc*Ee);       // [PCH]

    int b  = blockIdx.y;
    int p0 = blockIdx.x * PCH;
    int cnt = Pp - p0; if (cnt > PCH) cnt = PCH;

    const float4* __restrict__ cb4 = (const float4*)(ce + (size_t)b * Cc * Ee);
    for (int j = threadIdx.x; j < Cc*Ee/4; j += 256)
        ((float4*)s_tab)[j] = cb4[j];
    const int* __restrict__ idb = g_ids + b*Pp + p0;
    for (int j = threadIdx.x; j < cnt; j += 256)
        s_id[j] = idb[j];
    __syncthreads();

    int lane = threadIdx.x & 31;
    int warp = threadIdx.x >> 5;
    float4* __restrict__ out = (float4*)(gn + ((size_t)b*Pp + p0)*Ee);

    int p = warp;
    for (; p + 8 < cnt; p += 16) {
        int c0 = s_id[p], c1 = s_id[p + 8];
        float4 v0 = ((const float4*)(s_tab + c0*Ee))[lane];
        float4 v1 = ((const float4*)(s_tab + c1*Ee))[lane];
        __stcs(&out[(size_t)p      *32 + lane], v0);
        __stcs(&out[(size_t)(p + 8)*32 + lane], v1);
    }
    for (; p < cnt; p += 8) {
        int c = s_id[p];
        float4 v = ((const float4*)(s_tab + c*Ee))[lane];
        __stcs(&out[(size_t)p*32 + lane], v);
    }
}

// ---------------- launch ----------------
extern "C" void kernel_launch(void* const* d_in, const int* in_sizes, int n_in,
                              void* d_out, int out_size) {
    const float* enc  = nullptr;
    const void*  ids  = nullptr;
    const float* W    = nullptr;
    const float* bias = nullptr;
    for (int i = 0; i < n_in; i++) {
        switch (in_sizes[i]) {
            case Bb*Pp*Ee: enc  = (const float*)d_in[i]; break;
            case Bb*Pp:    ids  = d_in[i];               break;
            case Ee*Ee:    W    = (const float*)d_in[i]; break;
            case Ee:       bias = (const float*)d_in[i]; break;
            default: break;
        }
    }

    float* ce = (float*)d_out;                       // [B, C, E]
    float* gn = (float*)d_out + (size_t)BC * Ee;     // [B, P, E]

    cudaFuncSetAttribute(k_proj,   cudaFuncAttributeMaxDynamicSharedMemorySize, PROJ_SMEM);
    cudaFuncSetAttribute(k_gather, cudaFuncAttributeMaxDynamicSharedMemorySize, GATHER_SMEM);

    k_init  <<<(Ee*Ee + 255)/256, 256>>>((const int*)ids, W);
    k_bucket<<<(Bb*Pp + 255)/256, 256>>>(ids);
    k_mean  <<<BC, 128>>>(enc);
    k_proj  <<<BC/16, 256, PROJ_SMEM>>>(bias, ce);
    k_gather<<<dim3((Pp + PCH - 1)/PCH, Bb), 256, GATHER_SMEM>>>(ce, gn);
}